// round 12
// baseline (speedup 1.0000x reference)
#include <cuda_runtime.h>
#include <cstddef>

// Problem constants
#define NSEQ 4096      // h*w = 64*64
#define BATCH 4
#define NHEADS 4
#define DHEAD 32
#define INNER 128      // NHEADS*DHEAD
#define CIN 256
#define QSCALE 0.25505569218815374f        // 32^-0.5 * log2(e)

// Scratch (allocation-free rule: __device__ globals)
// g_qkv stored as fp16 pairs packed along n (h2 = {n, n+1}); Q rows pre-scaled.
__device__ unsigned g_qkvh[(size_t)BATCH * 3 * INNER * NSEQ / 2];  // (b,384,n/2)
__device__ float    g_att[(size_t)BATCH * INNER * NSEQ];           // (b,128,n)

// ---------------------------------------------------------------------------
// Helpers
// ---------------------------------------------------------------------------
__device__ __forceinline__ unsigned f2h2(float hi, float lo) {
    unsigned r;
    asm("cvt.rn.f16x2.f32 %0, %1, %2;" : "=r"(r) : "f"(hi), "f"(lo));
    return r;
}

__device__ __forceinline__ unsigned prmtb(unsigned a, unsigned b, unsigned sel) {
    unsigned d;
    asm("prmt.b32 %0, %1, %2, %3;" : "=r"(d) : "r"(a), "r"(b), "r"(sel));
    return d;
}

__device__ __forceinline__ unsigned ex2h2(unsigned x) {
    unsigned y;
    asm("ex2.approx.f16x2 %0, %1;" : "=r"(y) : "r"(x));
    return y;
}

__device__ __forceinline__ void mma_f16(float d[4], const unsigned a[4],
                                        const unsigned b[2], const float c[4]) {
    asm volatile(
        "mma.sync.aligned.m16n8k16.row.col.f32.f16.f16.f32 "
        "{%0,%1,%2,%3}, {%4,%5,%6,%7}, {%8,%9}, {%10,%11,%12,%13};\n"
        : "=f"(d[0]), "=f"(d[1]), "=f"(d[2]), "=f"(d[3])
        : "r"(a[0]), "r"(a[1]), "r"(a[2]), "r"(a[3]),
          "r"(b[0]), "r"(b[1]),
          "f"(c[0]), "f"(c[1]), "f"(c[2]), "f"(c[3]));
}

// ---------------------------------------------------------------------------
// fp16 tensor-core GEMM (unchanged from R11). Y = W X (+bias).
// Tile 64m x 128n x 32k, 8 warps. OUT_H2: emit half2 along n; QROWS_SCALE:
// scale rows <128 by QSCALE in fp32 before the fp16 round.
// ---------------------------------------------------------------------------
template <int K, int MTOT, bool HAS_BIAS, bool OUT_H2, bool QROWS_SCALE>
__device__ __forceinline__ void gemm_tc_body(const float* __restrict__ W,
                                             const float* __restrict__ X,
                                             const float* __restrict__ bias,
                                             void* __restrict__ Yv) {
    const int N = NSEQ;
    const int b  = blockIdx.z;
    const int o0 = blockIdx.y * 64;
    const int n0 = blockIdx.x * 128;
    const float* Xb = X + (size_t)b * K * N;

    __shared__ unsigned Wh[64][20];    // [m][k/2] f16x2 packed along k
    __shared__ unsigned Xh[16][136];   // [k/2][n] f16x2 packed along k

    const int t = threadIdx.x;
    const int warp = t >> 5;
    const int lane = t & 31;
    const int g = lane >> 2;
    const int tig = lane & 3;
    const int m0 = (warp & 3) * 16;
    const int nw = (warp >> 2) * 64;

    const int w_m  = t >> 3;
    const int w_k4 = (t & 7) << 2;
    const int x_dp = t >> 4;
    const int x_nv = (t & 15) << 3;

    float4 wreg[2], x0a, x0b, x1a, x1b;
#pragma unroll
    for (int r = 0; r < 2; r++)
        wreg[r] = *(const float4*)&W[(size_t)(o0 + w_m + 32 * r) * K + w_k4];
    x0a = *(const float4*)&Xb[(size_t)(2 * x_dp) * N + n0 + x_nv];
    x0b = *(const float4*)&Xb[(size_t)(2 * x_dp) * N + n0 + x_nv + 4];
    x1a = *(const float4*)&Xb[(size_t)(2 * x_dp + 1) * N + n0 + x_nv];
    x1b = *(const float4*)&Xb[(size_t)(2 * x_dp + 1) * N + n0 + x_nv + 4];

    float acc[8][4];
#pragma unroll
    for (int nn = 0; nn < 8; nn++)
#pragma unroll
        for (int c = 0; c < 4; c++) acc[nn][c] = 0.f;

#pragma unroll 1
    for (int c0 = 0; c0 < K; c0 += 32) {
#pragma unroll
        for (int r = 0; r < 2; r++) {
            uint2 wu = make_uint2(f2h2(wreg[r].y, wreg[r].x),
                                  f2h2(wreg[r].w, wreg[r].z));
            *(uint2*)&Wh[w_m + 32 * r][w_k4 >> 1] = wu;
        }
        {
            uint4 xa = make_uint4(f2h2(x1a.x, x0a.x), f2h2(x1a.y, x0a.y),
                                  f2h2(x1a.z, x0a.z), f2h2(x1a.w, x0a.w));
            *(uint4*)&Xh[x_dp][x_nv] = xa;
            uint4 xb = make_uint4(f2h2(x1b.x, x0b.x), f2h2(x1b.y, x0b.y),
                                  f2h2(x1b.z, x0b.z), f2h2(x1b.w, x0b.w));
            *(uint4*)&Xh[x_dp][x_nv + 4] = xb;
        }
        __syncthreads();

        if (c0 + 32 < K) {
#pragma unroll
            for (int r = 0; r < 2; r++)
                wreg[r] = *(const float4*)&W[(size_t)(o0 + w_m + 32 * r) * K + c0 + 32 + w_k4];
            x0a = *(const float4*)&Xb[(size_t)(c0 + 32 + 2 * x_dp) * N + n0 + x_nv];
            x0b = *(const float4*)&Xb[(size_t)(c0 + 32 + 2 * x_dp) * N + n0 + x_nv + 4];
            x1a = *(const float4*)&Xb[(size_t)(c0 + 32 + 2 * x_dp + 1) * N + n0 + x_nv];
            x1b = *(const float4*)&Xb[(size_t)(c0 + 32 + 2 * x_dp + 1) * N + n0 + x_nv + 4];
        }

#pragma unroll
        for (int ks = 0; ks < 2; ks++) {
            unsigned afr[4];
            afr[0] = Wh[m0 + g][8 * ks + tig];
            afr[1] = Wh[m0 + g + 8][8 * ks + tig];
            afr[2] = Wh[m0 + g][8 * ks + tig + 4];
            afr[3] = Wh[m0 + g + 8][8 * ks + tig + 4];
#pragma unroll
            for (int nn = 0; nn < 8; nn++) {
                unsigned bfr[2];
                bfr[0] = Xh[8 * ks + tig][nw + 8 * nn + g];
                bfr[1] = Xh[8 * ks + tig + 4][nw + 8 * nn + g];
                mma_f16(acc[nn], afr, bfr, acc[nn]);
            }
        }
        __syncthreads();
    }

    const int orow0 = o0 + m0 + g;
    const int orow1 = orow0 + 8;

    if (OUT_H2) {
        unsigned* Yh = (unsigned*)Yv + (size_t)b * MTOT * (N >> 1);
        const float sc = (QROWS_SCALE && o0 < 128) ? QSCALE : 1.f;
#pragma unroll
        for (int nn = 0; nn < 8; nn++) {
            int nh = (n0 + nw + 8 * nn + 2 * tig) >> 1;
            Yh[(size_t)orow0 * (N >> 1) + nh] = f2h2(acc[nn][1] * sc, acc[nn][0] * sc);
            Yh[(size_t)orow1 * (N >> 1) + nh] = f2h2(acc[nn][3] * sc, acc[nn][2] * sc);
        }
    } else {
        float* Yb = (float*)Yv + (size_t)b * MTOT * N;
        float b0 = 0.f, b1 = 0.f;
        if (HAS_BIAS) { b0 = bias[orow0]; b1 = bias[orow1]; }
#pragma unroll
        for (int nn = 0; nn < 8; nn++) {
            int n = n0 + nw + 8 * nn + 2 * tig;
            float2 r0 = make_float2(acc[nn][0] + b0, acc[nn][1] + b0);
            float2 r1 = make_float2(acc[nn][2] + b1, acc[nn][3] + b1);
            *(float2*)&Yb[(size_t)orow0 * N + n] = r0;
            *(float2*)&Yb[(size_t)orow1 * N + n] = r1;
        }
    }
}

__global__ void __launch_bounds__(256)
gemm_qkv_tc_kernel(const float* __restrict__ W, const float* __restrict__ X) {
    gemm_tc_body<CIN, 3 * INNER, false, true, true>(W, X, nullptr, (void*)g_qkvh);
}

__global__ void __launch_bounds__(256)
gemm_out_tc_kernel(const float* __restrict__ W, const float* __restrict__ bias,
                   float* __restrict__ Y) {
    gemm_tc_body<INNER, CIN, true, false, false>(W, g_att, bias, (void*)Y);
}

// ---------------------------------------------------------------------------
// Flash attention (R11 base) with kk-INTERLEAVED S -> exp2 -> PV:
// S for key-chunk kk only feeds PV A-fragments of chunk kk, so live S
// accumulators shrink 64 -> 16 regs. __launch_bounds__(128, 4) targets
// 4 CTAs/SM (16 warps) for latency hiding.
// ---------------------------------------------------------------------------
#define BM 128
#define BN 64

__global__ void __launch_bounds__(128, 4)
flash_attn_mma_kernel() {
    const int N2 = NSEQ / 2;               // row stride in h2 units
    const int bh = blockIdx.y;
    const int b = bh >> 2;
    const int h = bh & 3;
    const unsigned* qb2 = g_qkvh + (size_t)(b * 384 + h * DHEAD) * N2;
    const unsigned* kb2 = qb2 + (size_t)128 * N2;
    const unsigned* vb2 = qb2 + (size_t)256 * N2;
    const int i0 = blockIdx.x * BM;

    __shared__ unsigned ksh2[16][72];   // K tile: [d/2][j] f16x2 along d
    __shared__ unsigned vh2[32][36];    // V tile: [d][j/2] f16x2 along j
    __shared__ unsigned qsh2[128][20];  // Q: [query][d/2] f16x2 along d

    const int t = threadIdx.x;
    const int warp = t >> 5;
    const int lane = t & 31;
    const int g = lane >> 2;
    const int tig = lane & 3;
    const int mw = warp * 32;           // warp owns 32 query rows

    const int kdp = t >> 4;             // 0..7
    const int kj  = (t & 15) << 2;      // key offset 0..60
    const int vd = t >> 3;              // 0..15
    const int jv = (t & 7) << 3;        // key offset 0..56

    // --- Prefetch first K/V tile (fp16) ---
    uint2 kra[2], krb[2];
    uint4 vr[2];
#pragma unroll
    for (int rr = 0; rr < 2; rr++) {
        int dp = kdp + 8 * rr;
        kra[rr] = *(const uint2*)&kb2[(size_t)(2 * dp) * N2 + (kj >> 1)];
        krb[rr] = *(const uint2*)&kb2[(size_t)(2 * dp + 1) * N2 + (kj >> 1)];
        int d = vd + 16 * rr;
        vr[rr] = *(const uint4*)&vb2[(size_t)d * N2 + (jv >> 1)];
    }

    // --- Stage Q (pre-scaled fp16; interleave d-pairs with prmt) ---
#pragma unroll
    for (int r = 0; r < 4; r++) {
        int idx = t + 128 * r;               // 0..511
        int dp = idx & 15;                   // d-pair 0..15
        int iq = (idx >> 4) << 2;            // query 0..124 step 4
        uint2 q0 = *(const uint2*)&qb2[(size_t)(2 * dp) * N2 + ((i0 + iq) >> 1)];
        uint2 q1 = *(const uint2*)&qb2[(size_t)(2 * dp + 1) * N2 + ((i0 + iq) >> 1)];
        qsh2[iq + 0][dp] = prmtb(q0.x, q1.x, 0x5410);
        qsh2[iq + 1][dp] = prmtb(q0.x, q1.x, 0x7632);
        qsh2[iq + 2][dp] = prmtb(q0.y, q1.y, 0x5410);
        qsh2[iq + 3][dp] = prmtb(q0.y, q1.y, 0x7632);
    }
    __syncthreads();

    // Preload Q A-fragments: 2 row-blocks x 2 k-steps
    unsigned qa[2][2][4];
#pragma unroll
    for (int rb = 0; rb < 2; rb++)
#pragma unroll
        for (int ks = 0; ks < 2; ks++) {
            int r = mw + 16 * rb + g;
            qa[rb][ks][0] = qsh2[r][8 * ks + tig];
            qa[rb][ks][1] = qsh2[r + 8][8 * ks + tig];
            qa[rb][ks][2] = qsh2[r][8 * ks + tig + 4];
            qa[rb][ks][3] = qsh2[r + 8][8 * ks + tig + 4];
        }

    float oacc[2][4][4];
#pragma unroll
    for (int rb = 0; rb < 2; rb++)
#pragma unroll
        for (int n = 0; n < 4; n++)
#pragma unroll
            for (int c = 0; c < 4; c++) oacc[rb][n][c] = 0.f;
    float lacc[2][4] = {{0.f, 0.f, 0.f, 0.f}, {0.f, 0.f, 0.f, 0.f}};

    const unsigned ONE2 = 0x3C003C00u;
    const unsigned onesb[2] = {ONE2, ONE2};

#pragma unroll 1
    for (int j0 = 0; j0 < NSEQ; j0 += BN) {
        __syncthreads();  // previous tile fully consumed
        // --- Commit prefetched K (prmt d-pair interleave) and V (copy) ---
#pragma unroll
        for (int rr = 0; rr < 2; rr++) {
            uint4 ku;
            ku.x = prmtb(kra[rr].x, krb[rr].x, 0x5410);
            ku.y = prmtb(kra[rr].x, krb[rr].x, 0x7632);
            ku.z = prmtb(kra[rr].y, krb[rr].y, 0x5410);
            ku.w = prmtb(kra[rr].y, krb[rr].y, 0x7632);
            *(uint4*)&ksh2[kdp + 8 * rr][kj] = ku;
            *(uint4*)&vh2[vd + 16 * rr][jv >> 1] = vr[rr];
        }
        __syncthreads();

        // --- Prefetch next tile ---
        if (j0 + BN < NSEQ) {
#pragma unroll
            for (int rr = 0; rr < 2; rr++) {
                int dp = kdp + 8 * rr;
                kra[rr] = *(const uint2*)&kb2[(size_t)(2 * dp) * N2 + ((j0 + BN + kj) >> 1)];
                krb[rr] = *(const uint2*)&kb2[(size_t)(2 * dp + 1) * N2 + ((j0 + BN + kj) >> 1)];
                int d = vd + 16 * rr;
                vr[rr] = *(const uint4*)&vb2[(size_t)d * N2 + ((j0 + BN + jv) >> 1)];
            }
        }

        // --- kk-interleaved: S(2 cols) -> exp2 -> PV(kk), small live sacc ---
#pragma unroll
        for (int kk = 0; kk < 4; kk++) {
            float sacc[2][2][4];
#pragma unroll
            for (int rb = 0; rb < 2; rb++)
#pragma unroll
                for (int nn = 0; nn < 2; nn++)
#pragma unroll
                    for (int c = 0; c < 4; c++) sacc[rb][nn][c] = 0.f;

#pragma unroll
            for (int ks = 0; ks < 2; ks++) {
#pragma unroll
                for (int nn = 0; nn < 2; nn++) {
                    int n = 2 * kk + nn;
                    unsigned bfr[2];
                    bfr[0] = ksh2[8 * ks + tig][8 * n + g];
                    bfr[1] = ksh2[8 * ks + tig + 4][8 * n + g];
                    mma_f16(sacc[0][nn], qa[0][ks], bfr, sacc[0][nn]);
                    mma_f16(sacc[1][nn], qa[1][ks], bfr, sacc[1][nn]);
                }
            }

            unsigned afr[2][4];
#pragma unroll
            for (int rb = 0; rb < 2; rb++) {
                afr[rb][0] = ex2h2(f2h2(sacc[rb][0][1], sacc[rb][0][0]));
                afr[rb][1] = ex2h2(f2h2(sacc[rb][0][3], sacc[rb][0][2]));
                afr[rb][2] = ex2h2(f2h2(sacc[rb][1][1], sacc[rb][1][0]));
                afr[rb][3] = ex2h2(f2h2(sacc[rb][1][3], sacc[rb][1][2]));
            }
#pragma unroll
            for (int nn = 0; nn < 4; nn++) {
                unsigned bfr[2];
                bfr[0] = vh2[8 * nn + g][8 * kk + tig];
                bfr[1] = vh2[8 * nn + g][8 * kk + tig + 4];
                mma_f16(oacc[0][nn], afr[0], bfr, oacc[0][nn]);
                mma_f16(oacc[1][nn], afr[1], bfr, oacc[1][nn]);
            }
            mma_f16(lacc[0], afr[0], onesb, lacc[0]);
            mma_f16(lacc[1], afr[1], onesb, lacc[1]);
        }
    }

    // --- Epilogue: normalize by tensor-computed l, write channel-major ---
    float* ob = g_att + (size_t)(b * INNER + h * DHEAD) * NSEQ;
#pragma unroll
    for (int rb = 0; rb < 2; rb++) {
        const float il0 = 1.f / lacc[rb][0];
        const float il1 = 1.f / lacc[rb][2];
        const int r0 = i0 + mw + 16 * rb + g;
        const int r1 = r0 + 8;
#pragma unroll
        for (int n = 0; n < 4; n++) {
            int d0 = 8 * n + 2 * tig;
            ob[(size_t)(d0)     * NSEQ + r0] = oacc[rb][n][0] * il0;
            ob[(size_t)(d0 + 1) * NSEQ + r0] = oacc[rb][n][1] * il0;
            ob[(size_t)(d0)     * NSEQ + r1] = oacc[rb][n][2] * il1;
            ob[(size_t)(d0 + 1) * NSEQ + r1] = oacc[rb][n][3] * il1;
        }
    }
}

// ---------------------------------------------------------------------------
// Launch: qkv GEMM (fp16 out, Q pre-scaled) -> flash attention -> out proj
// ---------------------------------------------------------------------------
extern "C" void kernel_launch(void* const* d_in, const int* in_sizes, int n_in,
                              void* d_out, int out_size) {
    const float* x      = (const float*)d_in[0];  // (4,256,64,64)
    const float* w_qkv  = (const float*)d_in[1];  // (384,256)
    const float* w_out  = (const float*)d_in[2];  // (256,128)
    const float* b_out  = (const float*)d_in[3];  // (256,)
    float* y = (float*)d_out;                     // (4,256,64,64)

    dim3 g1(NSEQ / 128, (3 * INNER) / 64, BATCH);  // (32, 6, 4)
    gemm_qkv_tc_kernel<<<g1, 256>>>(w_qkv, x);

    dim3 g2(NSEQ / BM, BATCH * NHEADS);            // (32, 16)
    flash_attn_mma_kernel<<<g2, 128>>>();

    dim3 g3(NSEQ / 128, CIN / 64, BATCH);          // (32, 4, 4)
    gemm_out_tc_kernel<<<g3, 256>>>(w_out, b_out, y);
}

// round 13
// speedup vs baseline: 1.0168x; 1.0168x over previous
#include <cuda_runtime.h>
#include <cstddef>

// Problem constants
#define NSEQ 4096      // h*w = 64*64
#define BATCH 4
#define NHEADS 4
#define DHEAD 32
#define INNER 128      // NHEADS*DHEAD
#define CIN 256
#define QSCALE 0.25505569218815374f        // 32^-0.5 * log2(e)

// Scratch (allocation-free rule: __device__ globals)
// g_qkv stored as fp16 pairs packed along n (h2 = {n, n+1}); Q rows pre-scaled.
__device__ unsigned g_qkvh[(size_t)BATCH * 3 * INNER * NSEQ / 2];  // (b,384,n/2)
__device__ float    g_att[(size_t)BATCH * INNER * NSEQ];           // (b,128,n)

// ---------------------------------------------------------------------------
// Helpers
// ---------------------------------------------------------------------------
__device__ __forceinline__ unsigned f2h2(float hi, float lo) {
    unsigned r;
    asm("cvt.rn.f16x2.f32 %0, %1, %2;" : "=r"(r) : "f"(hi), "f"(lo));
    return r;
}

__device__ __forceinline__ unsigned prmtb(unsigned a, unsigned b, unsigned sel) {
    unsigned d;
    asm("prmt.b32 %0, %1, %2, %3;" : "=r"(d) : "r"(a), "r"(b), "r"(sel));
    return d;
}

__device__ __forceinline__ unsigned ex2h2(unsigned x) {
    unsigned y;
    asm("ex2.approx.f16x2 %0, %1;" : "=r"(y) : "r"(x));
    return y;
}

__device__ __forceinline__ void mma_f16(float d[4], const unsigned a[4],
                                        const unsigned b[2], const float c[4]) {
    asm volatile(
        "mma.sync.aligned.m16n8k16.row.col.f32.f16.f16.f32 "
        "{%0,%1,%2,%3}, {%4,%5,%6,%7}, {%8,%9}, {%10,%11,%12,%13};\n"
        : "=f"(d[0]), "=f"(d[1]), "=f"(d[2]), "=f"(d[3])
        : "r"(a[0]), "r"(a[1]), "r"(a[2]), "r"(a[3]),
          "r"(b[0]), "r"(b[1]),
          "f"(c[0]), "f"(c[1]), "f"(c[2]), "f"(c[3]));
}

// ---------------------------------------------------------------------------
// fp16 tensor-core GEMM (unchanged from R11). Y = W X (+bias).
// ---------------------------------------------------------------------------
template <int K, int MTOT, bool HAS_BIAS, bool OUT_H2, bool QROWS_SCALE>
__device__ __forceinline__ void gemm_tc_body(const float* __restrict__ W,
                                             const float* __restrict__ X,
                                             const float* __restrict__ bias,
                                             void* __restrict__ Yv) {
    const int N = NSEQ;
    const int b  = blockIdx.z;
    const int o0 = blockIdx.y * 64;
    const int n0 = blockIdx.x * 128;
    const float* Xb = X + (size_t)b * K * N;

    __shared__ unsigned Wh[64][20];    // [m][k/2] f16x2 packed along k
    __shared__ unsigned Xh[16][136];   // [k/2][n] f16x2 packed along k

    const int t = threadIdx.x;
    const int warp = t >> 5;
    const int lane = t & 31;
    const int g = lane >> 2;
    const int tig = lane & 3;
    const int m0 = (warp & 3) * 16;
    const int nw = (warp >> 2) * 64;

    const int w_m  = t >> 3;
    const int w_k4 = (t & 7) << 2;
    const int x_dp = t >> 4;
    const int x_nv = (t & 15) << 3;

    float4 wreg[2], x0a, x0b, x1a, x1b;
#pragma unroll
    for (int r = 0; r < 2; r++)
        wreg[r] = *(const float4*)&W[(size_t)(o0 + w_m + 32 * r) * K + w_k4];
    x0a = *(const float4*)&Xb[(size_t)(2 * x_dp) * N + n0 + x_nv];
    x0b = *(const float4*)&Xb[(size_t)(2 * x_dp) * N + n0 + x_nv + 4];
    x1a = *(const float4*)&Xb[(size_t)(2 * x_dp + 1) * N + n0 + x_nv];
    x1b = *(const float4*)&Xb[(size_t)(2 * x_dp + 1) * N + n0 + x_nv + 4];

    float acc[8][4];
#pragma unroll
    for (int nn = 0; nn < 8; nn++)
#pragma unroll
        for (int c = 0; c < 4; c++) acc[nn][c] = 0.f;

#pragma unroll 1
    for (int c0 = 0; c0 < K; c0 += 32) {
#pragma unroll
        for (int r = 0; r < 2; r++) {
            uint2 wu = make_uint2(f2h2(wreg[r].y, wreg[r].x),
                                  f2h2(wreg[r].w, wreg[r].z));
            *(uint2*)&Wh[w_m + 32 * r][w_k4 >> 1] = wu;
        }
        {
            uint4 xa = make_uint4(f2h2(x1a.x, x0a.x), f2h2(x1a.y, x0a.y),
                                  f2h2(x1a.z, x0a.z), f2h2(x1a.w, x0a.w));
            *(uint4*)&Xh[x_dp][x_nv] = xa;
            uint4 xb = make_uint4(f2h2(x1b.x, x0b.x), f2h2(x1b.y, x0b.y),
                                  f2h2(x1b.z, x0b.z), f2h2(x1b.w, x0b.w));
            *(uint4*)&Xh[x_dp][x_nv + 4] = xb;
        }
        __syncthreads();

        if (c0 + 32 < K) {
#pragma unroll
            for (int r = 0; r < 2; r++)
                wreg[r] = *(const float4*)&W[(size_t)(o0 + w_m + 32 * r) * K + c0 + 32 + w_k4];
            x0a = *(const float4*)&Xb[(size_t)(c0 + 32 + 2 * x_dp) * N + n0 + x_nv];
            x0b = *(const float4*)&Xb[(size_t)(c0 + 32 + 2 * x_dp) * N + n0 + x_nv + 4];
            x1a = *(const float4*)&Xb[(size_t)(c0 + 32 + 2 * x_dp + 1) * N + n0 + x_nv];
            x1b = *(const float4*)&Xb[(size_t)(c0 + 32 + 2 * x_dp + 1) * N + n0 + x_nv + 4];
        }

#pragma unroll
        for (int ks = 0; ks < 2; ks++) {
            unsigned afr[4];
            afr[0] = Wh[m0 + g][8 * ks + tig];
            afr[1] = Wh[m0 + g + 8][8 * ks + tig];
            afr[2] = Wh[m0 + g][8 * ks + tig + 4];
            afr[3] = Wh[m0 + g + 8][8 * ks + tig + 4];
#pragma unroll
            for (int nn = 0; nn < 8; nn++) {
                unsigned bfr[2];
                bfr[0] = Xh[8 * ks + tig][nw + 8 * nn + g];
                bfr[1] = Xh[8 * ks + tig + 4][nw + 8 * nn + g];
                mma_f16(acc[nn], afr, bfr, acc[nn]);
            }
        }
        __syncthreads();
    }

    const int orow0 = o0 + m0 + g;
    const int orow1 = orow0 + 8;

    if (OUT_H2) {
        unsigned* Yh = (unsigned*)Yv + (size_t)b * MTOT * (N >> 1);
        const float sc = (QROWS_SCALE && o0 < 128) ? QSCALE : 1.f;
#pragma unroll
        for (int nn = 0; nn < 8; nn++) {
            int nh = (n0 + nw + 8 * nn + 2 * tig) >> 1;
            Yh[(size_t)orow0 * (N >> 1) + nh] = f2h2(acc[nn][1] * sc, acc[nn][0] * sc);
            Yh[(size_t)orow1 * (N >> 1) + nh] = f2h2(acc[nn][3] * sc, acc[nn][2] * sc);
        }
    } else {
        float* Yb = (float*)Yv + (size_t)b * MTOT * N;
        float b0 = 0.f, b1 = 0.f;
        if (HAS_BIAS) { b0 = bias[orow0]; b1 = bias[orow1]; }
#pragma unroll
        for (int nn = 0; nn < 8; nn++) {
            int n = n0 + nw + 8 * nn + 2 * tig;
            float2 r0 = make_float2(acc[nn][0] + b0, acc[nn][1] + b0);
            float2 r1 = make_float2(acc[nn][2] + b1, acc[nn][3] + b1);
            *(float2*)&Yb[(size_t)orow0 * N + n] = r0;
            *(float2*)&Yb[(size_t)orow1 * N + n] = r1;
        }
    }
}

__global__ void __launch_bounds__(256)
gemm_qkv_tc_kernel(const float* __restrict__ W, const float* __restrict__ X) {
    gemm_tc_body<CIN, 3 * INNER, false, true, true>(W, X, nullptr, (void*)g_qkvh);
}

__global__ void __launch_bounds__(256)
gemm_out_tc_kernel(const float* __restrict__ W, const float* __restrict__ bias,
                   float* __restrict__ Y) {
    gemm_tc_body<INNER, CIN, true, false, false>(W, g_att, bias, (void*)Y);
}

// ---------------------------------------------------------------------------
// Flash attention, BM=256: 8 warps x 32 query rows, 256 threads/CTA.
// Halves CTA count (256 total) -> K/V L2 read traffic halves (256->128 MB)
// and total loader/sync work halves. Per-warp inner loop identical to R12
// (kk-interleaved S -> exp2 -> PV, register-resident P, tensor-core l).
// ---------------------------------------------------------------------------
#define BM 256
#define BN 64

__global__ void __launch_bounds__(256, 2)
flash_attn_mma_kernel() {
    const int N2 = NSEQ / 2;               // row stride in h2 units
    const int bh = blockIdx.y;
    const int b = bh >> 2;
    const int h = bh & 3;
    const unsigned* qb2 = g_qkvh + (size_t)(b * 384 + h * DHEAD) * N2;
    const unsigned* kb2 = qb2 + (size_t)128 * N2;
    const unsigned* vb2 = qb2 + (size_t)256 * N2;
    const int i0 = blockIdx.x * BM;

    __shared__ unsigned ksh2[16][72];   // K tile: [d/2][j] f16x2 along d
    __shared__ unsigned vh2[32][36];    // V tile: [d][j/2] f16x2 along j
    __shared__ unsigned qsh2[256][20];  // Q: [query][d/2] f16x2 along d

    const int t = threadIdx.x;
    const int warp = t >> 5;
    const int lane = t & 31;
    const int g = lane >> 2;
    const int tig = lane & 3;
    const int mw = warp * 32;           // warp owns 32 query rows

    // K loader: 256 threads cover all 16 d-pair rows x 16 j-segments
    const int kdp = t >> 4;             // 0..15
    const int kj  = (t & 15) << 2;      // key offset 0..60
    // V loader: 256 threads cover all 32 d rows x 8 j-segments
    const int vd = t >> 3;              // 0..31
    const int jv = (t & 7) << 3;        // key offset 0..56

    // --- Prefetch first K/V tile (fp16) ---
    uint2 kra, krb;
    uint4 vr;
    kra = *(const uint2*)&kb2[(size_t)(2 * kdp) * N2 + (kj >> 1)];
    krb = *(const uint2*)&kb2[(size_t)(2 * kdp + 1) * N2 + (kj >> 1)];
    vr  = *(const uint4*)&vb2[(size_t)vd * N2 + (jv >> 1)];

    // --- Stage Q (pre-scaled fp16; interleave d-pairs with prmt) ---
#pragma unroll
    for (int r = 0; r < 4; r++) {
        int idx = t + 256 * r;               // 0..1023
        int dp = idx & 15;                   // d-pair 0..15
        int iq = (idx >> 4) << 2;            // query 0..252 step 4
        uint2 q0 = *(const uint2*)&qb2[(size_t)(2 * dp) * N2 + ((i0 + iq) >> 1)];
        uint2 q1 = *(const uint2*)&qb2[(size_t)(2 * dp + 1) * N2 + ((i0 + iq) >> 1)];
        qsh2[iq + 0][dp] = prmtb(q0.x, q1.x, 0x5410);
        qsh2[iq + 1][dp] = prmtb(q0.x, q1.x, 0x7632);
        qsh2[iq + 2][dp] = prmtb(q0.y, q1.y, 0x5410);
        qsh2[iq + 3][dp] = prmtb(q0.y, q1.y, 0x7632);
    }
    __syncthreads();

    // Preload Q A-fragments: 2 row-blocks x 2 k-steps
    unsigned qa[2][2][4];
#pragma unroll
    for (int rb = 0; rb < 2; rb++)
#pragma unroll
        for (int ks = 0; ks < 2; ks++) {
            int r = mw + 16 * rb + g;
            qa[rb][ks][0] = qsh2[r][8 * ks + tig];
            qa[rb][ks][1] = qsh2[r + 8][8 * ks + tig];
            qa[rb][ks][2] = qsh2[r][8 * ks + tig + 4];
            qa[rb][ks][3] = qsh2[r + 8][8 * ks + tig + 4];
        }

    float oacc[2][4][4];
#pragma unroll
    for (int rb = 0; rb < 2; rb++)
#pragma unroll
        for (int n = 0; n < 4; n++)
#pragma unroll
            for (int c = 0; c < 4; c++) oacc[rb][n][c] = 0.f;
    float lacc[2][4] = {{0.f, 0.f, 0.f, 0.f}, {0.f, 0.f, 0.f, 0.f}};

    const unsigned ONE2 = 0x3C003C00u;
    const unsigned onesb[2] = {ONE2, ONE2};

#pragma unroll 1
    for (int j0 = 0; j0 < NSEQ; j0 += BN) {
        __syncthreads();  // previous tile fully consumed
        // --- Commit prefetched K (prmt d-pair interleave) and V (copy) ---
        {
            uint4 ku;
            ku.x = prmtb(kra.x, krb.x, 0x5410);
            ku.y = prmtb(kra.x, krb.x, 0x7632);
            ku.z = prmtb(kra.y, krb.y, 0x5410);
            ku.w = prmtb(kra.y, krb.y, 0x7632);
            *(uint4*)&ksh2[kdp][kj] = ku;
            *(uint4*)&vh2[vd][jv >> 1] = vr;
        }
        __syncthreads();

        // --- Prefetch next tile ---
        if (j0 + BN < NSEQ) {
            kra = *(const uint2*)&kb2[(size_t)(2 * kdp) * N2 + ((j0 + BN + kj) >> 1)];
            krb = *(const uint2*)&kb2[(size_t)(2 * kdp + 1) * N2 + ((j0 + BN + kj) >> 1)];
            vr  = *(const uint4*)&vb2[(size_t)vd * N2 + ((j0 + BN + jv) >> 1)];
        }

        // --- kk-interleaved: S(2 cols) -> exp2 -> PV(kk) ---
#pragma unroll
        for (int kk = 0; kk < 4; kk++) {
            float sacc[2][2][4];
#pragma unroll
            for (int rb = 0; rb < 2; rb++)
#pragma unroll
                for (int nn = 0; nn < 2; nn++)
#pragma unroll
                    for (int c = 0; c < 4; c++) sacc[rb][nn][c] = 0.f;

#pragma unroll
            for (int ks = 0; ks < 2; ks++) {
#pragma unroll
                for (int nn = 0; nn < 2; nn++) {
                    int n = 2 * kk + nn;
                    unsigned bfr[2];
                    bfr[0] = ksh2[8 * ks + tig][8 * n + g];
                    bfr[1] = ksh2[8 * ks + tig + 4][8 * n + g];
                    mma_f16(sacc[0][nn], qa[0][ks], bfr, sacc[0][nn]);
                    mma_f16(sacc[1][nn], qa[1][ks], bfr, sacc[1][nn]);
                }
            }

            unsigned afr[2][4];
#pragma unroll
            for (int rb = 0; rb < 2; rb++) {
                afr[rb][0] = ex2h2(f2h2(sacc[rb][0][1], sacc[rb][0][0]));
                afr[rb][1] = ex2h2(f2h2(sacc[rb][0][3], sacc[rb][0][2]));
                afr[rb][2] = ex2h2(f2h2(sacc[rb][1][1], sacc[rb][1][0]));
                afr[rb][3] = ex2h2(f2h2(sacc[rb][1][3], sacc[rb][1][2]));
            }
#pragma unroll
            for (int nn = 0; nn < 4; nn++) {
                unsigned bfr[2];
                bfr[0] = vh2[8 * nn + g][8 * kk + tig];
                bfr[1] = vh2[8 * nn + g][8 * kk + tig + 4];
                mma_f16(oacc[0][nn], afr[0], bfr, oacc[0][nn]);
                mma_f16(oacc[1][nn], afr[1], bfr, oacc[1][nn]);
            }
            mma_f16(lacc[0], afr[0], onesb, lacc[0]);
            mma_f16(lacc[1], afr[1], onesb, lacc[1]);
        }
    }

    // --- Epilogue: normalize by tensor-computed l, write channel-major ---
    float* ob = g_att + (size_t)(b * INNER + h * DHEAD) * NSEQ;
#pragma unroll
    for (int rb = 0; rb < 2; rb++) {
        const float il0 = 1.f / lacc[rb][0];
        const float il1 = 1.f / lacc[rb][2];
        const int r0 = i0 + mw + 16 * rb + g;
        const int r1 = r0 + 8;
#pragma unroll
        for (int n = 0; n < 4; n++) {
            int d0 = 8 * n + 2 * tig;
            ob[(size_t)(d0)     * NSEQ + r0] = oacc[rb][n][0] * il0;
            ob[(size_t)(d0 + 1) * NSEQ + r0] = oacc[rb][n][1] * il0;
            ob[(size_t)(d0)     * NSEQ + r1] = oacc[rb][n][2] * il1;
            ob[(size_t)(d0 + 1) * NSEQ + r1] = oacc[rb][n][3] * il1;
        }
    }
}

// ---------------------------------------------------------------------------
// Launch: qkv GEMM (fp16 out, Q pre-scaled) -> flash attention -> out proj
// ---------------------------------------------------------------------------
extern "C" void kernel_launch(void* const* d_in, const int* in_sizes, int n_in,
                              void* d_out, int out_size) {
    const float* x      = (const float*)d_in[0];  // (4,256,64,64)
    const float* w_qkv  = (const float*)d_in[1];  // (384,256)
    const float* w_out  = (const float*)d_in[2];  // (256,128)
    const float* b_out  = (const float*)d_in[3];  // (256,)
    float* y = (float*)d_out;                     // (4,256,64,64)

    dim3 g1(NSEQ / 128, (3 * INNER) / 64, BATCH);  // (32, 6, 4)
    gemm_qkv_tc_kernel<<<g1, 256>>>(w_qkv, x);

    dim3 g2(NSEQ / BM, BATCH * NHEADS);            // (16, 16)
    flash_attn_mma_kernel<<<g2, 256>>>();

    dim3 g3(NSEQ / 128, CIN / 64, BATCH);          // (32, 4, 4)
    gemm_out_tc_kernel<<<g3, 256>>>(w_out, b_out, y);
}

// round 14
// speedup vs baseline: 1.1104x; 1.0921x over previous
#include <cuda_runtime.h>
#include <cstddef>

// Problem constants
#define NSEQ 4096      // h*w = 64*64
#define BATCH 4
#define NHEADS 4
#define DHEAD 32
#define INNER 128      // NHEADS*DHEAD
#define CIN 256
#define QSCALE 0.25505569218815374f        // 32^-0.5 * log2(e)

// Scratch (allocation-free rule: __device__ globals)
// g_qkvh: fp16 pairs packed along n; Q rows pre-scaled by QSCALE.
// g_atth: fp16 pairs packed along d (= proj GEMM's k) -> proj loads it raw.
__device__ unsigned g_qkvh[(size_t)BATCH * 3 * INNER * NSEQ / 2];  // (b,384,n/2)
__device__ unsigned g_atth[(size_t)BATCH * (INNER / 2) * NSEQ];    // (b,64,n) h2-d

// ---------------------------------------------------------------------------
// Helpers
// ---------------------------------------------------------------------------
__device__ __forceinline__ unsigned f2h2(float hi, float lo) {
    unsigned r;
    asm("cvt.rn.f16x2.f32 %0, %1, %2;" : "=r"(r) : "f"(hi), "f"(lo));
    return r;
}

__device__ __forceinline__ unsigned prmtb(unsigned a, unsigned b, unsigned sel) {
    unsigned d;
    asm("prmt.b32 %0, %1, %2, %3;" : "=r"(d) : "r"(a), "r"(b), "r"(sel));
    return d;
}

__device__ __forceinline__ unsigned ex2h2(unsigned x) {
    unsigned y;
    asm("ex2.approx.f16x2 %0, %1;" : "=r"(y) : "r"(x));
    return y;
}

__device__ __forceinline__ void mma_f16(float d[4], const unsigned a[4],
                                        const unsigned b[2], const float c[4]) {
    asm volatile(
        "mma.sync.aligned.m16n8k16.row.col.f32.f16.f16.f32 "
        "{%0,%1,%2,%3}, {%4,%5,%6,%7}, {%8,%9}, {%10,%11,%12,%13};\n"
        : "=f"(d[0]), "=f"(d[1]), "=f"(d[2]), "=f"(d[3])
        : "r"(a[0]), "r"(a[1]), "r"(a[2]), "r"(a[3]),
          "r"(b[0]), "r"(b[1]),
          "f"(c[0]), "f"(c[1]), "f"(c[2]), "f"(c[3]));
}

// ---------------------------------------------------------------------------
// fp16 tensor-core GEMM, tile 128m x 128n x 32k (o-tile doubled vs R13 so X
// is re-read 3x/2x instead of 6x/4x -- the L1-bound term). 8 warps (4m x 2n),
// each warp 32m x 64n (2 row-blocks). IN_H2: X is already fp16 k-pair-packed
// (g_atth) -> commit is a raw copy. OUT_H2/QROWS_SCALE as before.
// ---------------------------------------------------------------------------
template <int K, int MTOT, bool HAS_BIAS, bool OUT_H2, bool QROWS_SCALE, bool IN_H2>
__device__ __forceinline__ void gemm_tc_body(const float* __restrict__ W,
                                             const void* __restrict__ Xv,
                                             const float* __restrict__ bias,
                                             void* __restrict__ Yv) {
    const int N = NSEQ;
    const int b  = blockIdx.z;
    const int o0 = blockIdx.y * 128;
    const int n0 = blockIdx.x * 128;

    __shared__ unsigned Wh[128][20];   // [m][k/2] f16x2 packed along k
    __shared__ unsigned Xh[16][136];   // [k/2][n] f16x2 packed along k

    const int t = threadIdx.x;
    const int warp = t >> 5;
    const int lane = t & 31;
    const int g = lane >> 2;
    const int tig = lane & 3;
    const int m0 = (warp & 3) * 32;    // warp m offset (32 rows)
    const int nw = (warp >> 2) * 64;   // warp n offset

    const int w_m  = t >> 3;           // 0..31 (+32/64/96)
    const int w_k4 = (t & 7) << 2;     // k offset 0..28
    const int x_dp = t >> 4;           // k-pair row 0..15
    const int x_nv = (t & 15) << 3;    // n offset 0..120

    // Prefetch state
    float4 wreg[4];
    float4 x0a, x0b, x1a, x1b;         // fp32 input path
    uint4 xh_a, xh_b;                  // fp16 input path

#define G_LOAD_W(c0)                                                            \
    do {                                                                        \
        _Pragma("unroll")                                                       \
        for (int r = 0; r < 4; r++)                                             \
            wreg[r] = *(const float4*)&W[(size_t)(o0 + w_m + 32 * r) * K + (c0) + w_k4]; \
    } while (0)

#define G_LOAD_X(c0)                                                            \
    do {                                                                        \
        if (IN_H2) {                                                            \
            const unsigned* Xh2 = (const unsigned*)Xv + (size_t)b * (K / 2) * N;\
            xh_a = *(const uint4*)&Xh2[(size_t)(((c0) >> 1) + x_dp) * N + n0 + x_nv]; \
            xh_b = *(const uint4*)&Xh2[(size_t)(((c0) >> 1) + x_dp) * N + n0 + x_nv + 4]; \
        } else {                                                                \
            const float* Xb = (const float*)Xv + (size_t)b * K * N;             \
            x0a = *(const float4*)&Xb[(size_t)((c0) + 2 * x_dp) * N + n0 + x_nv];\
            x0b = *(const float4*)&Xb[(size_t)((c0) + 2 * x_dp) * N + n0 + x_nv + 4];\
            x1a = *(const float4*)&Xb[(size_t)((c0) + 2 * x_dp + 1) * N + n0 + x_nv];\
            x1b = *(const float4*)&Xb[(size_t)((c0) + 2 * x_dp + 1) * N + n0 + x_nv + 4];\
        }                                                                       \
    } while (0)

#define G_COMMIT()                                                              \
    do {                                                                        \
        _Pragma("unroll")                                                       \
        for (int r = 0; r < 4; r++) {                                           \
            uint2 wu = make_uint2(f2h2(wreg[r].y, wreg[r].x),                   \
                                  f2h2(wreg[r].w, wreg[r].z));                  \
            *(uint2*)&Wh[w_m + 32 * r][w_k4 >> 1] = wu;                         \
        }                                                                       \
        if (IN_H2) {                                                            \
            *(uint4*)&Xh[x_dp][x_nv] = xh_a;                                    \
            *(uint4*)&Xh[x_dp][x_nv + 4] = xh_b;                                \
        } else {                                                                \
            uint4 xa = make_uint4(f2h2(x1a.x, x0a.x), f2h2(x1a.y, x0a.y),       \
                                  f2h2(x1a.z, x0a.z), f2h2(x1a.w, x0a.w));      \
            *(uint4*)&Xh[x_dp][x_nv] = xa;                                      \
            uint4 xb = make_uint4(f2h2(x1b.x, x0b.x), f2h2(x1b.y, x0b.y),       \
                                  f2h2(x1b.z, x0b.z), f2h2(x1b.w, x0b.w));      \
            *(uint4*)&Xh[x_dp][x_nv + 4] = xb;                                  \
        }                                                                       \
    } while (0)

    float acc[2][8][4];
#pragma unroll
    for (int rb = 0; rb < 2; rb++)
#pragma unroll
        for (int nn = 0; nn < 8; nn++)
#pragma unroll
            for (int c = 0; c < 4; c++) acc[rb][nn][c] = 0.f;

    G_LOAD_W(0);
    G_LOAD_X(0);

#pragma unroll 1
    for (int c0 = 0; c0 < K; c0 += 32) {
        G_COMMIT();
        __syncthreads();

        if (c0 + 32 < K) {
            G_LOAD_W(c0 + 32);
            G_LOAD_X(c0 + 32);
        }

#pragma unroll
        for (int ks = 0; ks < 2; ks++) {
            unsigned afr[2][4];
#pragma unroll
            for (int rb = 0; rb < 2; rb++) {
                int r = m0 + 16 * rb + g;
                afr[rb][0] = Wh[r][8 * ks + tig];
                afr[rb][1] = Wh[r + 8][8 * ks + tig];
                afr[rb][2] = Wh[r][8 * ks + tig + 4];
                afr[rb][3] = Wh[r + 8][8 * ks + tig + 4];
            }
#pragma unroll
            for (int nn = 0; nn < 8; nn++) {
                unsigned bfr[2];
                bfr[0] = Xh[8 * ks + tig][nw + 8 * nn + g];
                bfr[1] = Xh[8 * ks + tig + 4][nw + 8 * nn + g];
                mma_f16(acc[0][nn], afr[0], bfr, acc[0][nn]);
                mma_f16(acc[1][nn], afr[1], bfr, acc[1][nn]);
            }
        }
        __syncthreads();
    }
#undef G_LOAD_W
#undef G_LOAD_X
#undef G_COMMIT

    // Epilogue
#pragma unroll
    for (int rb = 0; rb < 2; rb++) {
        const int orow0 = o0 + m0 + 16 * rb + g;
        const int orow1 = orow0 + 8;
        if (OUT_H2) {
            unsigned* Yh = (unsigned*)Yv + (size_t)b * MTOT * (N >> 1);
            const float sc = (QROWS_SCALE && o0 < 128) ? QSCALE : 1.f;
#pragma unroll
            for (int nn = 0; nn < 8; nn++) {
                int nh = (n0 + nw + 8 * nn + 2 * tig) >> 1;
                Yh[(size_t)orow0 * (N >> 1) + nh] = f2h2(acc[rb][nn][1] * sc, acc[rb][nn][0] * sc);
                Yh[(size_t)orow1 * (N >> 1) + nh] = f2h2(acc[rb][nn][3] * sc, acc[rb][nn][2] * sc);
            }
        } else {
            float* Yb = (float*)Yv + (size_t)b * MTOT * N;
            float b0 = 0.f, b1 = 0.f;
            if (HAS_BIAS) { b0 = bias[orow0]; b1 = bias[orow1]; }
#pragma unroll
            for (int nn = 0; nn < 8; nn++) {
                int n = n0 + nw + 8 * nn + 2 * tig;
                float2 r0 = make_float2(acc[rb][nn][0] + b0, acc[rb][nn][1] + b0);
                float2 r1 = make_float2(acc[rb][nn][2] + b1, acc[rb][nn][3] + b1);
                *(float2*)&Yb[(size_t)orow0 * N + n] = r0;
                *(float2*)&Yb[(size_t)orow1 * N + n] = r1;
            }
        }
    }
}

__global__ void __launch_bounds__(256)
gemm_qkv_tc_kernel(const float* __restrict__ W, const float* __restrict__ X) {
    gemm_tc_body<CIN, 3 * INNER, false, true, true, false>(W, (const void*)X,
                                                           nullptr, (void*)g_qkvh);
}

__global__ void __launch_bounds__(256)
gemm_out_tc_kernel(const float* __restrict__ W, const float* __restrict__ bias,
                   float* __restrict__ Y) {
    gemm_tc_body<INNER, CIN, true, false, false, true>(W, (const void*)g_atth,
                                                       bias, (void*)Y);
}

// ---------------------------------------------------------------------------
// Flash attention (R13 config): BM=256, 8 warps x 32 query rows, 256 threads.
// kk-interleaved S -> exp2 -> PV, register-resident P, tensor-core l.
// Epilogue now writes g_atth (fp16 packed along d = proj's k layout).
// ---------------------------------------------------------------------------
#define BM 256
#define BN 64

__global__ void __launch_bounds__(256, 2)
flash_attn_mma_kernel() {
    const int N2 = NSEQ / 2;               // row stride in h2 units
    const int bh = blockIdx.y;
    const int b = bh >> 2;
    const int h = bh & 3;
    const unsigned* qb2 = g_qkvh + (size_t)(b * 384 + h * DHEAD) * N2;
    const unsigned* kb2 = qb2 + (size_t)128 * N2;
    const unsigned* vb2 = qb2 + (size_t)256 * N2;
    const int i0 = blockIdx.x * BM;

    __shared__ unsigned ksh2[16][72];   // K tile: [d/2][j] f16x2 along d
    __shared__ unsigned vh2[32][36];    // V tile: [d][j/2] f16x2 along j
    __shared__ unsigned qsh2[256][20];  // Q: [query][d/2] f16x2 along d

    const int t = threadIdx.x;
    const int warp = t >> 5;
    const int lane = t & 31;
    const int g = lane >> 2;
    const int tig = lane & 3;
    const int mw = warp * 32;           // warp owns 32 query rows

    const int kdp = t >> 4;             // 0..15
    const int kj  = (t & 15) << 2;      // key offset 0..60
    const int vd = t >> 3;              // 0..31
    const int jv = (t & 7) << 3;        // key offset 0..56

    // --- Prefetch first K/V tile (fp16) ---
    uint2 kra, krb;
    uint4 vr;
    kra = *(const uint2*)&kb2[(size_t)(2 * kdp) * N2 + (kj >> 1)];
    krb = *(const uint2*)&kb2[(size_t)(2 * kdp + 1) * N2 + (kj >> 1)];
    vr  = *(const uint4*)&vb2[(size_t)vd * N2 + (jv >> 1)];

    // --- Stage Q (pre-scaled fp16; interleave d-pairs with prmt) ---
#pragma unroll
    for (int r = 0; r < 4; r++) {
        int idx = t + 256 * r;               // 0..1023
        int dp = idx & 15;                   // d-pair 0..15
        int iq = (idx >> 4) << 2;            // query 0..252 step 4
        uint2 q0 = *(const uint2*)&qb2[(size_t)(2 * dp) * N2 + ((i0 + iq) >> 1)];
        uint2 q1 = *(const uint2*)&qb2[(size_t)(2 * dp + 1) * N2 + ((i0 + iq) >> 1)];
        qsh2[iq + 0][dp] = prmtb(q0.x, q1.x, 0x5410);
        qsh2[iq + 1][dp] = prmtb(q0.x, q1.x, 0x7632);
        qsh2[iq + 2][dp] = prmtb(q0.y, q1.y, 0x5410);
        qsh2[iq + 3][dp] = prmtb(q0.y, q1.y, 0x7632);
    }
    __syncthreads();

    // Preload Q A-fragments: 2 row-blocks x 2 k-steps
    unsigned qa[2][2][4];
#pragma unroll
    for (int rb = 0; rb < 2; rb++)
#pragma unroll
        for (int ks = 0; ks < 2; ks++) {
            int r = mw + 16 * rb + g;
            qa[rb][ks][0] = qsh2[r][8 * ks + tig];
            qa[rb][ks][1] = qsh2[r + 8][8 * ks + tig];
            qa[rb][ks][2] = qsh2[r][8 * ks + tig + 4];
            qa[rb][ks][3] = qsh2[r + 8][8 * ks + tig + 4];
        }

    float oacc[2][4][4];
#pragma unroll
    for (int rb = 0; rb < 2; rb++)
#pragma unroll
        for (int n = 0; n < 4; n++)
#pragma unroll
            for (int c = 0; c < 4; c++) oacc[rb][n][c] = 0.f;
    float lacc[2][4] = {{0.f, 0.f, 0.f, 0.f}, {0.f, 0.f, 0.f, 0.f}};

    const unsigned ONE2 = 0x3C003C00u;
    const unsigned onesb[2] = {ONE2, ONE2};

#pragma unroll 1
    for (int j0 = 0; j0 < NSEQ; j0 += BN) {
        __syncthreads();  // previous tile fully consumed
        // --- Commit prefetched K (prmt d-pair interleave) and V (copy) ---
        {
            uint4 ku;
            ku.x = prmtb(kra.x, krb.x, 0x5410);
            ku.y = prmtb(kra.x, krb.x, 0x7632);
            ku.z = prmtb(kra.y, krb.y, 0x5410);
            ku.w = prmtb(kra.y, krb.y, 0x7632);
            *(uint4*)&ksh2[kdp][kj] = ku;
            *(uint4*)&vh2[vd][jv >> 1] = vr;
        }
        __syncthreads();

        // --- Prefetch next tile ---
        if (j0 + BN < NSEQ) {
            kra = *(const uint2*)&kb2[(size_t)(2 * kdp) * N2 + ((j0 + BN + kj) >> 1)];
            krb = *(const uint2*)&kb2[(size_t)(2 * kdp + 1) * N2 + ((j0 + BN + kj) >> 1)];
            vr  = *(const uint4*)&vb2[(size_t)vd * N2 + ((j0 + BN + jv) >> 1)];
        }

        // --- kk-interleaved: S(2 cols) -> exp2 -> PV(kk) ---
#pragma unroll
        for (int kk = 0; kk < 4; kk++) {
            float sacc[2][2][4];
#pragma unroll
            for (int rb = 0; rb < 2; rb++)
#pragma unroll
                for (int nn = 0; nn < 2; nn++)
#pragma unroll
                    for (int c = 0; c < 4; c++) sacc[rb][nn][c] = 0.f;

#pragma unroll
            for (int ks = 0; ks < 2; ks++) {
#pragma unroll
                for (int nn = 0; nn < 2; nn++) {
                    int n = 2 * kk + nn;
                    unsigned bfr[2];
                    bfr[0] = ksh2[8 * ks + tig][8 * n + g];
                    bfr[1] = ksh2[8 * ks + tig + 4][8 * n + g];
                    mma_f16(sacc[0][nn], qa[0][ks], bfr, sacc[0][nn]);
                    mma_f16(sacc[1][nn], qa[1][ks], bfr, sacc[1][nn]);
                }
            }

            unsigned afr[2][4];
#pragma unroll
            for (int rb = 0; rb < 2; rb++) {
                afr[rb][0] = ex2h2(f2h2(sacc[rb][0][1], sacc[rb][0][0]));
                afr[rb][1] = ex2h2(f2h2(sacc[rb][0][3], sacc[rb][0][2]));
                afr[rb][2] = ex2h2(f2h2(sacc[rb][1][1], sacc[rb][1][0]));
                afr[rb][3] = ex2h2(f2h2(sacc[rb][1][3], sacc[rb][1][2]));
            }
#pragma unroll
            for (int nn = 0; nn < 4; nn++) {
                unsigned bfr[2];
                bfr[0] = vh2[8 * nn + g][8 * kk + tig];
                bfr[1] = vh2[8 * nn + g][8 * kk + tig + 4];
                mma_f16(oacc[0][nn], afr[0], bfr, oacc[0][nn]);
                mma_f16(oacc[1][nn], afr[1], bfr, oacc[1][nn]);
            }
            mma_f16(lacc[0], afr[0], onesb, lacc[0]);
            mma_f16(lacc[1], afr[1], onesb, lacc[1]);
        }
    }

    // --- Epilogue: normalize, write fp16 d-pair-packed g_atth ---
    unsigned* obh = g_atth + (size_t)(b * (INNER / 2) + h * (DHEAD / 2)) * NSEQ;
#pragma unroll
    for (int rb = 0; rb < 2; rb++) {
        const float il0 = 1.f / lacc[rb][0];
        const float il1 = 1.f / lacc[rb][2];
        const int r0 = i0 + mw + 16 * rb + g;
        const int r1 = r0 + 8;
#pragma unroll
        for (int n = 0; n < 4; n++) {
            int dp = 4 * n + tig;            // d-pair row (d0=8n+2tig)/2
            obh[(size_t)dp * NSEQ + r0] = f2h2(oacc[rb][n][1] * il0, oacc[rb][n][0] * il0);
            obh[(size_t)dp * NSEQ + r1] = f2h2(oacc[rb][n][3] * il1, oacc[rb][n][2] * il1);
        }
    }
}

// ---------------------------------------------------------------------------
// Launch: qkv GEMM -> flash attention -> output projection
// ---------------------------------------------------------------------------
extern "C" void kernel_launch(void* const* d_in, const int* in_sizes, int n_in,
                              void* d_out, int out_size) {
    const float* x      = (const float*)d_in[0];  // (4,256,64,64)
    const float* w_qkv  = (const float*)d_in[1];  // (384,256)
    const float* w_out  = (const float*)d_in[2];  // (256,128)
    const float* b_out  = (const float*)d_in[3];  // (256,)
    float* y = (float*)d_out;                     // (4,256,64,64)

    dim3 g1(NSEQ / 128, (3 * INNER) / 128, BATCH); // (32, 3, 4)
    gemm_qkv_tc_kernel<<<g1, 256>>>(w_qkv, x);

    dim3 g2(NSEQ / BM, BATCH * NHEADS);            // (16, 16)
    flash_attn_mma_kernel<<<g2, 256>>>();

    dim3 g3(NSEQ / 128, CIN / 128, BATCH);         // (32, 2, 4)
    gemm_out_tc_kernel<<<g3, 256>>>(w_out, b_out, y);
}

// round 15
// speedup vs baseline: 1.1653x; 1.0494x over previous
#include <cuda_runtime.h>
#include <cstddef>

// Problem constants
#define NSEQ 4096      // h*w = 64*64
#define BATCH 4
#define NHEADS 4
#define DHEAD 32
#define INNER 128      // NHEADS*DHEAD
#define CIN 256
#define QSCALE 0.25505569218815374f        // 32^-0.5 * log2(e)

// Scratch (allocation-free rule: __device__ globals)
// g_qkvh: fp16 pairs packed along n; Q rows pre-scaled by QSCALE.
// g_atth: fp16 pairs packed along d (= proj GEMM's k) -> proj loads it raw.
__device__ unsigned g_qkvh[(size_t)BATCH * 3 * INNER * NSEQ / 2];  // (b,384,n/2)
__device__ unsigned g_atth[(size_t)BATCH * (INNER / 2) * NSEQ];    // (b,64,n) h2-d

// ---------------------------------------------------------------------------
// Helpers
// ---------------------------------------------------------------------------
__device__ __forceinline__ unsigned f2h2(float hi, float lo) {
    unsigned r;
    asm("cvt.rn.f16x2.f32 %0, %1, %2;" : "=r"(r) : "f"(hi), "f"(lo));
    return r;
}

__device__ __forceinline__ unsigned prmtb(unsigned a, unsigned b, unsigned sel) {
    unsigned d;
    asm("prmt.b32 %0, %1, %2, %3;" : "=r"(d) : "r"(a), "r"(b), "r"(sel));
    return d;
}

__device__ __forceinline__ unsigned ex2h2(unsigned x) {
    unsigned y;
    asm("ex2.approx.f16x2 %0, %1;" : "=r"(y) : "r"(x));
    return y;
}

// fp32-accumulate fp16 MMA (O, l — long accumulation chains stay fp32)
__device__ __forceinline__ void mma_f16(float d[4], const unsigned a[4],
                                        const unsigned b[2], const float c[4]) {
    asm volatile(
        "mma.sync.aligned.m16n8k16.row.col.f32.f16.f16.f32 "
        "{%0,%1,%2,%3}, {%4,%5,%6,%7}, {%8,%9}, {%10,%11,%12,%13};\n"
        : "=f"(d[0]), "=f"(d[1]), "=f"(d[2]), "=f"(d[3])
        : "r"(a[0]), "r"(a[1]), "r"(a[2]), "r"(a[3]),
          "r"(b[0]), "r"(b[1]),
          "f"(c[0]), "f"(c[1]), "f"(c[2]), "f"(c[3]));
}

// fp16-accumulate fp16 MMA (S — fresh 32-term dot per tile; D regs are
// pre-packed half2 {row g}/{row g+8}, feeding ex2h2 directly)
__device__ __forceinline__ void mma_f16h(unsigned d[2], const unsigned a[4],
                                         const unsigned b[2], const unsigned c[2]) {
    asm volatile(
        "mma.sync.aligned.m16n8k16.row.col.f16.f16.f16.f16 "
        "{%0,%1}, {%2,%3,%4,%5}, {%6,%7}, {%8,%9};\n"
        : "=r"(d[0]), "=r"(d[1])
        : "r"(a[0]), "r"(a[1]), "r"(a[2]), "r"(a[3]),
          "r"(b[0]), "r"(b[1]),
          "r"(c[0]), "r"(c[1]));
}

// ---------------------------------------------------------------------------
// fp16 tensor-core GEMM (unchanged from R14): tile 128m x 128n x 32k, 8 warps.
// ---------------------------------------------------------------------------
template <int K, int MTOT, bool HAS_BIAS, bool OUT_H2, bool QROWS_SCALE, bool IN_H2>
__device__ __forceinline__ void gemm_tc_body(const float* __restrict__ W,
                                             const void* __restrict__ Xv,
                                             const float* __restrict__ bias,
                                             void* __restrict__ Yv) {
    const int N = NSEQ;
    const int b  = blockIdx.z;
    const int o0 = blockIdx.y * 128;
    const int n0 = blockIdx.x * 128;

    __shared__ unsigned Wh[128][20];   // [m][k/2] f16x2 packed along k
    __shared__ unsigned Xh[16][136];   // [k/2][n] f16x2 packed along k

    const int t = threadIdx.x;
    const int warp = t >> 5;
    const int lane = t & 31;
    const int g = lane >> 2;
    const int tig = lane & 3;
    const int m0 = (warp & 3) * 32;
    const int nw = (warp >> 2) * 64;

    const int w_m  = t >> 3;
    const int w_k4 = (t & 7) << 2;
    const int x_dp = t >> 4;
    const int x_nv = (t & 15) << 3;

    float4 wreg[4];
    float4 x0a, x0b, x1a, x1b;
    uint4 xh_a, xh_b;

#define G_LOAD_W(c0)                                                            \
    do {                                                                        \
        _Pragma("unroll")                                                       \
        for (int r = 0; r < 4; r++)                                             \
            wreg[r] = *(const float4*)&W[(size_t)(o0 + w_m + 32 * r) * K + (c0) + w_k4]; \
    } while (0)

#define G_LOAD_X(c0)                                                            \
    do {                                                                        \
        if (IN_H2) {                                                            \
            const unsigned* Xh2 = (const unsigned*)Xv + (size_t)b * (K / 2) * N;\
            xh_a = *(const uint4*)&Xh2[(size_t)(((c0) >> 1) + x_dp) * N + n0 + x_nv]; \
            xh_b = *(const uint4*)&Xh2[(size_t)(((c0) >> 1) + x_dp) * N + n0 + x_nv + 4]; \
        } else {                                                                \
            const float* Xb = (const float*)Xv + (size_t)b * K * N;             \
            x0a = *(const float4*)&Xb[(size_t)((c0) + 2 * x_dp) * N + n0 + x_nv];\
            x0b = *(const float4*)&Xb[(size_t)((c0) + 2 * x_dp) * N + n0 + x_nv + 4];\
            x1a = *(const float4*)&Xb[(size_t)((c0) + 2 * x_dp + 1) * N + n0 + x_nv];\
            x1b = *(const float4*)&Xb[(size_t)((c0) + 2 * x_dp + 1) * N + n0 + x_nv + 4];\
        }                                                                       \
    } while (0)

#define G_COMMIT()                                                              \
    do {                                                                        \
        _Pragma("unroll")                                                       \
        for (int r = 0; r < 4; r++) {                                           \
            uint2 wu = make_uint2(f2h2(wreg[r].y, wreg[r].x),                   \
                                  f2h2(wreg[r].w, wreg[r].z));                  \
            *(uint2*)&Wh[w_m + 32 * r][w_k4 >> 1] = wu;                         \
        }                                                                       \
        if (IN_H2) {                                                            \
            *(uint4*)&Xh[x_dp][x_nv] = xh_a;                                    \
            *(uint4*)&Xh[x_dp][x_nv + 4] = xh_b;                                \
        } else {                                                                \
            uint4 xa = make_uint4(f2h2(x1a.x, x0a.x), f2h2(x1a.y, x0a.y),       \
                                  f2h2(x1a.z, x0a.z), f2h2(x1a.w, x0a.w));      \
            *(uint4*)&Xh[x_dp][x_nv] = xa;                                      \
            uint4 xb = make_uint4(f2h2(x1b.x, x0b.x), f2h2(x1b.y, x0b.y),       \
                                  f2h2(x1b.z, x0b.z), f2h2(x1b.w, x0b.w));      \
            *(uint4*)&Xh[x_dp][x_nv + 4] = xb;                                  \
        }                                                                       \
    } while (0)

    float acc[2][8][4];
#pragma unroll
    for (int rb = 0; rb < 2; rb++)
#pragma unroll
        for (int nn = 0; nn < 8; nn++)
#pragma unroll
            for (int c = 0; c < 4; c++) acc[rb][nn][c] = 0.f;

    G_LOAD_W(0);
    G_LOAD_X(0);

#pragma unroll 1
    for (int c0 = 0; c0 < K; c0 += 32) {
        G_COMMIT();
        __syncthreads();

        if (c0 + 32 < K) {
            G_LOAD_W(c0 + 32);
            G_LOAD_X(c0 + 32);
        }

#pragma unroll
        for (int ks = 0; ks < 2; ks++) {
            unsigned afr[2][4];
#pragma unroll
            for (int rb = 0; rb < 2; rb++) {
                int r = m0 + 16 * rb + g;
                afr[rb][0] = Wh[r][8 * ks + tig];
                afr[rb][1] = Wh[r + 8][8 * ks + tig];
                afr[rb][2] = Wh[r][8 * ks + tig + 4];
                afr[rb][3] = Wh[r + 8][8 * ks + tig + 4];
            }
#pragma unroll
            for (int nn = 0; nn < 8; nn++) {
                unsigned bfr[2];
                bfr[0] = Xh[8 * ks + tig][nw + 8 * nn + g];
                bfr[1] = Xh[8 * ks + tig + 4][nw + 8 * nn + g];
                mma_f16(acc[0][nn], afr[0], bfr, acc[0][nn]);
                mma_f16(acc[1][nn], afr[1], bfr, acc[1][nn]);
            }
        }
        __syncthreads();
    }
#undef G_LOAD_W
#undef G_LOAD_X
#undef G_COMMIT

#pragma unroll
    for (int rb = 0; rb < 2; rb++) {
        const int orow0 = o0 + m0 + 16 * rb + g;
        const int orow1 = orow0 + 8;
        if (OUT_H2) {
            unsigned* Yh = (unsigned*)Yv + (size_t)b * MTOT * (N >> 1);
            const float sc = (QROWS_SCALE && o0 < 128) ? QSCALE : 1.f;
#pragma unroll
            for (int nn = 0; nn < 8; nn++) {
                int nh = (n0 + nw + 8 * nn + 2 * tig) >> 1;
                Yh[(size_t)orow0 * (N >> 1) + nh] = f2h2(acc[rb][nn][1] * sc, acc[rb][nn][0] * sc);
                Yh[(size_t)orow1 * (N >> 1) + nh] = f2h2(acc[rb][nn][3] * sc, acc[rb][nn][2] * sc);
            }
        } else {
            float* Yb = (float*)Yv + (size_t)b * MTOT * N;
            float b0 = 0.f, b1 = 0.f;
            if (HAS_BIAS) { b0 = bias[orow0]; b1 = bias[orow1]; }
#pragma unroll
            for (int nn = 0; nn < 8; nn++) {
                int n = n0 + nw + 8 * nn + 2 * tig;
                float2 r0 = make_float2(acc[rb][nn][0] + b0, acc[rb][nn][1] + b0);
                float2 r1 = make_float2(acc[rb][nn][2] + b1, acc[rb][nn][3] + b1);
                *(float2*)&Yb[(size_t)orow0 * N + n] = r0;
                *(float2*)&Yb[(size_t)orow1 * N + n] = r1;
            }
        }
    }
}

__global__ void __launch_bounds__(256)
gemm_qkv_tc_kernel(const float* __restrict__ W, const float* __restrict__ X) {
    gemm_tc_body<CIN, 3 * INNER, false, true, true, false>(W, (const void*)X,
                                                           nullptr, (void*)g_qkvh);
}

__global__ void __launch_bounds__(256)
gemm_out_tc_kernel(const float* __restrict__ W, const float* __restrict__ bias,
                   float* __restrict__ Y) {
    gemm_tc_body<INNER, CIN, true, false, false, true>(W, (const void*)g_atth,
                                                       bias, (void*)Y);
}

// ---------------------------------------------------------------------------
// Flash attention (R14 config) with S in fp16-ACCUMULATE MMA:
// S D-fragments are packed half2 {row g}/{row g+8} == exactly the PV A-frag
// halves, so P = ex2h2(sd) directly (no f2h2 packing at all).
// O and l remain fp32-accumulate (4096-long chains).
// ---------------------------------------------------------------------------
#define BM 256
#define BN 64

__global__ void __launch_bounds__(256, 2)
flash_attn_mma_kernel() {
    const int N2 = NSEQ / 2;               // row stride in h2 units
    const int bh = blockIdx.y;
    const int b = bh >> 2;
    const int h = bh & 3;
    const unsigned* qb2 = g_qkvh + (size_t)(b * 384 + h * DHEAD) * N2;
    const unsigned* kb2 = qb2 + (size_t)128 * N2;
    const unsigned* vb2 = qb2 + (size_t)256 * N2;
    const int i0 = blockIdx.x * BM;

    __shared__ unsigned ksh2[16][72];   // K tile: [d/2][j] f16x2 along d
    __shared__ unsigned vh2[32][36];    // V tile: [d][j/2] f16x2 along j
    __shared__ unsigned qsh2[256][20];  // Q: [query][d/2] f16x2 along d

    const int t = threadIdx.x;
    const int warp = t >> 5;
    const int lane = t & 31;
    const int g = lane >> 2;
    const int tig = lane & 3;
    const int mw = warp * 32;           // warp owns 32 query rows

    const int kdp = t >> 4;             // 0..15
    const int kj  = (t & 15) << 2;      // key offset 0..60
    const int vd = t >> 3;              // 0..31
    const int jv = (t & 7) << 3;        // key offset 0..56

    // --- Prefetch first K/V tile (fp16) ---
    uint2 kra, krb;
    uint4 vr;
    kra = *(const uint2*)&kb2[(size_t)(2 * kdp) * N2 + (kj >> 1)];
    krb = *(const uint2*)&kb2[(size_t)(2 * kdp + 1) * N2 + (kj >> 1)];
    vr  = *(const uint4*)&vb2[(size_t)vd * N2 + (jv >> 1)];

    // --- Stage Q (pre-scaled fp16; interleave d-pairs with prmt) ---
#pragma unroll
    for (int r = 0; r < 4; r++) {
        int idx = t + 256 * r;               // 0..1023
        int dp = idx & 15;                   // d-pair 0..15
        int iq = (idx >> 4) << 2;            // query 0..252 step 4
        uint2 q0 = *(const uint2*)&qb2[(size_t)(2 * dp) * N2 + ((i0 + iq) >> 1)];
        uint2 q1 = *(const uint2*)&qb2[(size_t)(2 * dp + 1) * N2 + ((i0 + iq) >> 1)];
        qsh2[iq + 0][dp] = prmtb(q0.x, q1.x, 0x5410);
        qsh2[iq + 1][dp] = prmtb(q0.x, q1.x, 0x7632);
        qsh2[iq + 2][dp] = prmtb(q0.y, q1.y, 0x5410);
        qsh2[iq + 3][dp] = prmtb(q0.y, q1.y, 0x7632);
    }
    __syncthreads();

    // Preload Q A-fragments: 2 row-blocks x 2 k-steps
    unsigned qa[2][2][4];
#pragma unroll
    for (int rb = 0; rb < 2; rb++)
#pragma unroll
        for (int ks = 0; ks < 2; ks++) {
            int r = mw + 16 * rb + g;
            qa[rb][ks][0] = qsh2[r][8 * ks + tig];
            qa[rb][ks][1] = qsh2[r + 8][8 * ks + tig];
            qa[rb][ks][2] = qsh2[r][8 * ks + tig + 4];
            qa[rb][ks][3] = qsh2[r + 8][8 * ks + tig + 4];
        }

    float oacc[2][4][4];
#pragma unroll
    for (int rb = 0; rb < 2; rb++)
#pragma unroll
        for (int n = 0; n < 4; n++)
#pragma unroll
            for (int c = 0; c < 4; c++) oacc[rb][n][c] = 0.f;
    float lacc[2][4] = {{0.f, 0.f, 0.f, 0.f}, {0.f, 0.f, 0.f, 0.f}};

    const unsigned ONE2 = 0x3C003C00u;
    const unsigned onesb[2] = {ONE2, ONE2};

#pragma unroll 1
    for (int j0 = 0; j0 < NSEQ; j0 += BN) {
        __syncthreads();  // previous tile fully consumed
        // --- Commit prefetched K (prmt d-pair interleave) and V (copy) ---
        {
            uint4 ku;
            ku.x = prmtb(kra.x, krb.x, 0x5410);
            ku.y = prmtb(kra.x, krb.x, 0x7632);
            ku.z = prmtb(kra.y, krb.y, 0x5410);
            ku.w = prmtb(kra.y, krb.y, 0x7632);
            *(uint4*)&ksh2[kdp][kj] = ku;
            *(uint4*)&vh2[vd][jv >> 1] = vr;
        }
        __syncthreads();

        // --- Prefetch next tile ---
        if (j0 + BN < NSEQ) {
            kra = *(const uint2*)&kb2[(size_t)(2 * kdp) * N2 + ((j0 + BN + kj) >> 1)];
            krb = *(const uint2*)&kb2[(size_t)(2 * kdp + 1) * N2 + ((j0 + BN + kj) >> 1)];
            vr  = *(const uint4*)&vb2[(size_t)vd * N2 + ((j0 + BN + jv) >> 1)];
        }

        // --- kk-interleaved: S (fp16-accum MMA) -> exp2 -> PV (fp32) ---
#pragma unroll
        for (int kk = 0; kk < 4; kk++) {
            unsigned sd[2][2][2];   // [rb][nn][reg]; reg0 = row g, reg1 = row g+8
#pragma unroll
            for (int rb = 0; rb < 2; rb++)
#pragma unroll
                for (int nn = 0; nn < 2; nn++) {
                    sd[rb][nn][0] = 0u;
                    sd[rb][nn][1] = 0u;
                }

#pragma unroll
            for (int ks = 0; ks < 2; ks++) {
#pragma unroll
                for (int nn = 0; nn < 2; nn++) {
                    int n = 2 * kk + nn;
                    unsigned bfr[2];
                    bfr[0] = ksh2[8 * ks + tig][8 * n + g];
                    bfr[1] = ksh2[8 * ks + tig + 4][8 * n + g];
                    mma_f16h(sd[0][nn], qa[0][ks], bfr, sd[0][nn]);
                    mma_f16h(sd[1][nn], qa[1][ks], bfr, sd[1][nn]);
                }
            }

            // P = exp2(S): D-fragments are already PV A-fragment halves
            unsigned afr[2][4];
#pragma unroll
            for (int rb = 0; rb < 2; rb++) {
                afr[rb][0] = ex2h2(sd[rb][0][0]);
                afr[rb][1] = ex2h2(sd[rb][0][1]);
                afr[rb][2] = ex2h2(sd[rb][1][0]);
                afr[rb][3] = ex2h2(sd[rb][1][1]);
            }
#pragma unroll
            for (int nn = 0; nn < 4; nn++) {
                unsigned bfr[2];
                bfr[0] = vh2[8 * nn + g][8 * kk + tig];
                bfr[1] = vh2[8 * nn + g][8 * kk + tig + 4];
                mma_f16(oacc[0][nn], afr[0], bfr, oacc[0][nn]);
                mma_f16(oacc[1][nn], afr[1], bfr, oacc[1][nn]);
            }
            mma_f16(lacc[0], afr[0], onesb, lacc[0]);
            mma_f16(lacc[1], afr[1], onesb, lacc[1]);
        }
    }

    // --- Epilogue: normalize, write fp16 d-pair-packed g_atth ---
    unsigned* obh = g_atth + (size_t)(b * (INNER / 2) + h * (DHEAD / 2)) * NSEQ;
#pragma unroll
    for (int rb = 0; rb < 2; rb++) {
        const float il0 = 1.f / lacc[rb][0];
        const float il1 = 1.f / lacc[rb][2];
        const int r0 = i0 + mw + 16 * rb + g;
        const int r1 = r0 + 8;
#pragma unroll
        for (int n = 0; n < 4; n++) {
            int dp = 4 * n + tig;            // d-pair row
            obh[(size_t)dp * NSEQ + r0] = f2h2(oacc[rb][n][1] * il0, oacc[rb][n][0] * il0);
            obh[(size_t)dp * NSEQ + r1] = f2h2(oacc[rb][n][3] * il1, oacc[rb][n][2] * il1);
        }
    }
}

// ---------------------------------------------------------------------------
// Launch: qkv GEMM -> flash attention -> output projection
// ---------------------------------------------------------------------------
extern "C" void kernel_launch(void* const* d_in, const int* in_sizes, int n_in,
                              void* d_out, int out_size) {
    const float* x      = (const float*)d_in[0];  // (4,256,64,64)
    const float* w_qkv  = (const float*)d_in[1];  // (384,256)
    const float* w_out  = (const float*)d_in[2];  // (256,128)
    const float* b_out  = (const float*)d_in[3];  // (256,)
    float* y = (float*)d_out;                     // (4,256,64,64)

    dim3 g1(NSEQ / 128, (3 * INNER) / 128, BATCH); // (32, 3, 4)
    gemm_qkv_tc_kernel<<<g1, 256>>>(w_qkv, x);

    dim3 g2(NSEQ / BM, BATCH * NHEADS);            // (16, 16)
    flash_attn_mma_kernel<<<g2, 256>>>();

    dim3 g3(NSEQ / 128, CIN / 128, BATCH);         // (32, 2, 4)
    gemm_out_tc_kernel<<<g3, 256>>>(w_out, b_out, y);
}

// round 17
// speedup vs baseline: 1.1691x; 1.0032x over previous
#include <cuda_runtime.h>
#include <cstddef>

// Problem constants
#define NSEQ 4096      // h*w = 64*64
#define BATCH 4
#define NHEADS 4
#define DHEAD 32
#define INNER 128      // NHEADS*DHEAD
#define CIN 256
#define QSCALE 0.25505569218815374f        // 32^-0.5 * log2(e)

// Scratch (allocation-free rule: __device__ globals)
__device__ unsigned g_qkvh[(size_t)BATCH * 3 * INNER * NSEQ / 2];  // (b,384,n/2)
__device__ unsigned g_atth[(size_t)BATCH * (INNER / 2) * NSEQ];    // (b,64,n) h2-d

// ---------------------------------------------------------------------------
// Helpers
// ---------------------------------------------------------------------------
__device__ __forceinline__ unsigned f2h2(float hi, float lo) {
    unsigned r;
    asm("cvt.rn.f16x2.f32 %0, %1, %2;" : "=r"(r) : "f"(hi), "f"(lo));
    return r;
}

__device__ __forceinline__ unsigned prmtb(unsigned a, unsigned b, unsigned sel) {
    unsigned d;
    asm("prmt.b32 %0, %1, %2, %3;" : "=r"(d) : "r"(a), "r"(b), "r"(sel));
    return d;
}

__device__ __forceinline__ unsigned ex2h2(unsigned x) {
    unsigned y;
    asm("ex2.approx.f16x2 %0, %1;" : "=r"(y) : "r"(x));
    return y;
}

__device__ __forceinline__ unsigned hadd2(unsigned a, unsigned b) {
    unsigned d;
    asm("add.f16x2 %0, %1, %2;" : "=r"(d) : "r"(a), "r"(b));
    return d;
}

// sum both halves of a half2 into fp32 (pure PTX, no cuda_fp16.h dependency)
__device__ __forceinline__ float h2sumf(unsigned h2) {
    float lo, hi;
    asm("{ .reg .f16 l, h;\n\t"
        "  mov.b32 {l, h}, %2;\n\t"
        "  cvt.f32.f16 %0, l;\n\t"
        "  cvt.f32.f16 %1, h; }"
        : "=f"(lo), "=f"(hi) : "r"(h2));
    return lo + hi;
}

// fp32-accumulate fp16 MMA (O — long accumulation chain stays fp32)
__device__ __forceinline__ void mma_f16(float d[4], const unsigned a[4],
                                        const unsigned b[2], const float c[4]) {
    asm volatile(
        "mma.sync.aligned.m16n8k16.row.col.f32.f16.f16.f32 "
        "{%0,%1,%2,%3}, {%4,%5,%6,%7}, {%8,%9}, {%10,%11,%12,%13};\n"
        : "=f"(d[0]), "=f"(d[1]), "=f"(d[2]), "=f"(d[3])
        : "r"(a[0]), "r"(a[1]), "r"(a[2]), "r"(a[3]),
          "r"(b[0]), "r"(b[1]),
          "f"(c[0]), "f"(c[1]), "f"(c[2]), "f"(c[3]));
}

// fp16-accumulate fp16 MMA (S — fresh 32-term dot; D = PV A-frag halves)
__device__ __forceinline__ void mma_f16h(unsigned d[2], const unsigned a[4],
                                         const unsigned b[2], const unsigned c[2]) {
    asm volatile(
        "mma.sync.aligned.m16n8k16.row.col.f16.f16.f16.f16 "
        "{%0,%1}, {%2,%3,%4,%5}, {%6,%7}, {%8,%9};\n"
        : "=r"(d[0]), "=r"(d[1])
        : "r"(a[0]), "r"(a[1]), "r"(a[2]), "r"(a[3]),
          "r"(b[0]), "r"(b[1]),
          "r"(c[0]), "r"(c[1]));
}

// ---------------------------------------------------------------------------
// fp16 tensor-core GEMM (unchanged from R14/R15): tile 128m x 128n x 32k.
// ---------------------------------------------------------------------------
template <int K, int MTOT, bool HAS_BIAS, bool OUT_H2, bool QROWS_SCALE, bool IN_H2>
__device__ __forceinline__ void gemm_tc_body(const float* __restrict__ W,
                                             const void* __restrict__ Xv,
                                             const float* __restrict__ bias,
                                             void* __restrict__ Yv) {
    const int N = NSEQ;
    const int b  = blockIdx.z;
    const int o0 = blockIdx.y * 128;
    const int n0 = blockIdx.x * 128;

    __shared__ unsigned Wh[128][20];   // [m][k/2] f16x2 packed along k
    __shared__ unsigned Xh[16][136];   // [k/2][n] f16x2 packed along k

    const int t = threadIdx.x;
    const int warp = t >> 5;
    const int lane = t & 31;
    const int g = lane >> 2;
    const int tig = lane & 3;
    const int m0 = (warp & 3) * 32;
    const int nw = (warp >> 2) * 64;

    const int w_m  = t >> 3;
    const int w_k4 = (t & 7) << 2;
    const int x_dp = t >> 4;
    const int x_nv = (t & 15) << 3;

    float4 wreg[4];
    float4 x0a, x0b, x1a, x1b;
    uint4 xh_a, xh_b;

#define G_LOAD_W(c0)                                                            \
    do {                                                                        \
        _Pragma("unroll")                                                       \
        for (int r = 0; r < 4; r++)                                             \
            wreg[r] = *(const float4*)&W[(size_t)(o0 + w_m + 32 * r) * K + (c0) + w_k4]; \
    } while (0)

#define G_LOAD_X(c0)                                                            \
    do {                                                                        \
        if (IN_H2) {                                                            \
            const unsigned* Xh2 = (const unsigned*)Xv + (size_t)b * (K / 2) * N;\
            xh_a = *(const uint4*)&Xh2[(size_t)(((c0) >> 1) + x_dp) * N + n0 + x_nv]; \
            xh_b = *(const uint4*)&Xh2[(size_t)(((c0) >> 1) + x_dp) * N + n0 + x_nv + 4]; \
        } else {                                                                \
            const float* Xb = (const float*)Xv + (size_t)b * K * N;             \
            x0a = *(const float4*)&Xb[(size_t)((c0) + 2 * x_dp) * N + n0 + x_nv];\
            x0b = *(const float4*)&Xb[(size_t)((c0) + 2 * x_dp) * N + n0 + x_nv + 4];\
            x1a = *(const float4*)&Xb[(size_t)((c0) + 2 * x_dp + 1) * N + n0 + x_nv];\
            x1b = *(const float4*)&Xb[(size_t)((c0) + 2 * x_dp + 1) * N + n0 + x_nv + 4];\
        }                                                                       \
    } while (0)

#define G_COMMIT()                                                              \
    do {                                                                        \
        _Pragma("unroll")                                                       \
        for (int r = 0; r < 4; r++) {                                           \
            uint2 wu = make_uint2(f2h2(wreg[r].y, wreg[r].x),                   \
                                  f2h2(wreg[r].w, wreg[r].z));                  \
            *(uint2*)&Wh[w_m + 32 * r][w_k4 >> 1] = wu;                         \
        }                                                                       \
        if (IN_H2) {                                                            \
            *(uint4*)&Xh[x_dp][x_nv] = xh_a;                                    \
            *(uint4*)&Xh[x_dp][x_nv + 4] = xh_b;                                \
        } else {                                                                \
            uint4 xa = make_uint4(f2h2(x1a.x, x0a.x), f2h2(x1a.y, x0a.y),       \
                                  f2h2(x1a.z, x0a.z), f2h2(x1a.w, x0a.w));      \
            *(uint4*)&Xh[x_dp][x_nv] = xa;                                      \
            uint4 xb = make_uint4(f2h2(x1b.x, x0b.x), f2h2(x1b.y, x0b.y),       \
                                  f2h2(x1b.z, x0b.z), f2h2(x1b.w, x0b.w));      \
            *(uint4*)&Xh[x_dp][x_nv + 4] = xb;                                  \
        }                                                                       \
    } while (0)

    float acc[2][8][4];
#pragma unroll
    for (int rb = 0; rb < 2; rb++)
#pragma unroll
        for (int nn = 0; nn < 8; nn++)
#pragma unroll
            for (int c = 0; c < 4; c++) acc[rb][nn][c] = 0.f;

    G_LOAD_W(0);
    G_LOAD_X(0);

#pragma unroll 1
    for (int c0 = 0; c0 < K; c0 += 32) {
        G_COMMIT();
        __syncthreads();

        if (c0 + 32 < K) {
            G_LOAD_W(c0 + 32);
            G_LOAD_X(c0 + 32);
        }

#pragma unroll
        for (int ks = 0; ks < 2; ks++) {
            unsigned afr[2][4];
#pragma unroll
            for (int rb = 0; rb < 2; rb++) {
                int r = m0 + 16 * rb + g;
                afr[rb][0] = Wh[r][8 * ks + tig];
                afr[rb][1] = Wh[r + 8][8 * ks + tig];
                afr[rb][2] = Wh[r][8 * ks + tig + 4];
                afr[rb][3] = Wh[r + 8][8 * ks + tig + 4];
            }
#pragma unroll
            for (int nn = 0; nn < 8; nn++) {
                unsigned bfr[2];
                bfr[0] = Xh[8 * ks + tig][nw + 8 * nn + g];
                bfr[1] = Xh[8 * ks + tig + 4][nw + 8 * nn + g];
                mma_f16(acc[0][nn], afr[0], bfr, acc[0][nn]);
                mma_f16(acc[1][nn], afr[1], bfr, acc[1][nn]);
            }
        }
        __syncthreads();
    }
#undef G_LOAD_W
#undef G_LOAD_X
#undef G_COMMIT

#pragma unroll
    for (int rb = 0; rb < 2; rb++) {
        const int orow0 = o0 + m0 + 16 * rb + g;
        const int orow1 = orow0 + 8;
        if (OUT_H2) {
            unsigned* Yh = (unsigned*)Yv + (size_t)b * MTOT * (N >> 1);
            const float sc = (QROWS_SCALE && o0 < 128) ? QSCALE : 1.f;
#pragma unroll
            for (int nn = 0; nn < 8; nn++) {
                int nh = (n0 + nw + 8 * nn + 2 * tig) >> 1;
                Yh[(size_t)orow0 * (N >> 1) + nh] = f2h2(acc[rb][nn][1] * sc, acc[rb][nn][0] * sc);
                Yh[(size_t)orow1 * (N >> 1) + nh] = f2h2(acc[rb][nn][3] * sc, acc[rb][nn][2] * sc);
            }
        } else {
            float* Yb = (float*)Yv + (size_t)b * MTOT * N;
            float b0 = 0.f, b1 = 0.f;
            if (HAS_BIAS) { b0 = bias[orow0]; b1 = bias[orow1]; }
#pragma unroll
            for (int nn = 0; nn < 8; nn++) {
                int n = n0 + nw + 8 * nn + 2 * tig;
                float2 r0 = make_float2(acc[rb][nn][0] + b0, acc[rb][nn][1] + b0);
                float2 r1 = make_float2(acc[rb][nn][2] + b1, acc[rb][nn][3] + b1);
                *(float2*)&Yb[(size_t)orow0 * N + n] = r0;
                *(float2*)&Yb[(size_t)orow1 * N + n] = r1;
            }
        }
    }
}

__global__ void __launch_bounds__(256)
gemm_qkv_tc_kernel(const float* __restrict__ W, const float* __restrict__ X) {
    gemm_tc_body<CIN, 3 * INNER, false, true, true, false>(W, (const void*)X,
                                                           nullptr, (void*)g_qkvh);
}

__global__ void __launch_bounds__(256)
gemm_out_tc_kernel(const float* __restrict__ W, const float* __restrict__ bias,
                   float* __restrict__ Y) {
    gemm_tc_body<INNER, CIN, true, false, false, true>(W, (const void*)g_atth,
                                                       bias, (void*)Y);
}

// ---------------------------------------------------------------------------
// Flash attention (R15 config) with l moved OFF the tensor pipe:
// per-kk HADD2 folds of the fp16 P fragments build per-tile half2 row-sum
// partials; per-tile promotion to fp32; quad shfl-reduce at epilogue.
// Removes 8 l-MMAs/warp-tile from the saturated tensor pipe.
// ---------------------------------------------------------------------------
#define BM 256
#define BN 64

__global__ void __launch_bounds__(256, 2)
flash_attn_mma_kernel() {
    const int N2 = NSEQ / 2;               // row stride in h2 units
    const int bh = blockIdx.y;
    const int b = bh >> 2;
    const int h = bh & 3;
    const unsigned* qb2 = g_qkvh + (size_t)(b * 384 + h * DHEAD) * N2;
    const unsigned* kb2 = qb2 + (size_t)128 * N2;
    const unsigned* vb2 = qb2 + (size_t)256 * N2;
    const int i0 = blockIdx.x * BM;

    __shared__ unsigned ksh2[16][72];   // K tile: [d/2][j] f16x2 along d
    __shared__ unsigned vh2[32][36];    // V tile: [d][j/2] f16x2 along j
    __shared__ unsigned qsh2[256][20];  // Q: [query][d/2] f16x2 along d

    const int t = threadIdx.x;
    const int warp = t >> 5;
    const int lane = t & 31;
    const int g = lane >> 2;
    const int tig = lane & 3;
    const int mw = warp * 32;           // warp owns 32 query rows

    const int kdp = t >> 4;             // 0..15
    const int kj  = (t & 15) << 2;      // key offset 0..60
    const int vd = t >> 3;              // 0..31
    const int jv = (t & 7) << 3;        // key offset 0..56

    // --- Prefetch first K/V tile (fp16) ---
    uint2 kra, krb;
    uint4 vr;
    kra = *(const uint2*)&kb2[(size_t)(2 * kdp) * N2 + (kj >> 1)];
    krb = *(const uint2*)&kb2[(size_t)(2 * kdp + 1) * N2 + (kj >> 1)];
    vr  = *(const uint4*)&vb2[(size_t)vd * N2 + (jv >> 1)];

    // --- Stage Q (pre-scaled fp16; interleave d-pairs with prmt) ---
#pragma unroll
    for (int r = 0; r < 4; r++) {
        int idx = t + 256 * r;               // 0..1023
        int dp = idx & 15;                   // d-pair 0..15
        int iq = (idx >> 4) << 2;            // query 0..252 step 4
        uint2 q0 = *(const uint2*)&qb2[(size_t)(2 * dp) * N2 + ((i0 + iq) >> 1)];
        uint2 q1 = *(const uint2*)&qb2[(size_t)(2 * dp + 1) * N2 + ((i0 + iq) >> 1)];
        qsh2[iq + 0][dp] = prmtb(q0.x, q1.x, 0x5410);
        qsh2[iq + 1][dp] = prmtb(q0.x, q1.x, 0x7632);
        qsh2[iq + 2][dp] = prmtb(q0.y, q1.y, 0x5410);
        qsh2[iq + 3][dp] = prmtb(q0.y, q1.y, 0x7632);
    }
    __syncthreads();

    // Preload Q A-fragments: 2 row-blocks x 2 k-steps
    unsigned qa[2][2][4];
#pragma unroll
    for (int rb = 0; rb < 2; rb++)
#pragma unroll
        for (int ks = 0; ks < 2; ks++) {
            int r = mw + 16 * rb + g;
            qa[rb][ks][0] = qsh2[r][8 * ks + tig];
            qa[rb][ks][1] = qsh2[r + 8][8 * ks + tig];
            qa[rb][ks][2] = qsh2[r][8 * ks + tig + 4];
            qa[rb][ks][3] = qsh2[r + 8][8 * ks + tig + 4];
        }

    float oacc[2][4][4];
#pragma unroll
    for (int rb = 0; rb < 2; rb++)
#pragma unroll
        for (int n = 0; n < 4; n++)
#pragma unroll
            for (int c = 0; c < 4; c++) oacc[rb][n][c] = 0.f;
    float lf[2][2] = {{0.f, 0.f}, {0.f, 0.f}};   // fp32 row-sum partials [rb][row g / g+8]

#pragma unroll 1
    for (int j0 = 0; j0 < NSEQ; j0 += BN) {
        __syncthreads();  // previous tile fully consumed
        // --- Commit prefetched K (prmt d-pair interleave) and V (copy) ---
        {
            uint4 ku;
            ku.x = prmtb(kra.x, krb.x, 0x5410);
            ku.y = prmtb(kra.x, krb.x, 0x7632);
            ku.z = prmtb(kra.y, krb.y, 0x5410);
            ku.w = prmtb(kra.y, krb.y, 0x7632);
            *(uint4*)&ksh2[kdp][kj] = ku;
            *(uint4*)&vh2[vd][jv >> 1] = vr;
        }
        __syncthreads();

        // --- Prefetch next tile ---
        if (j0 + BN < NSEQ) {
            kra = *(const uint2*)&kb2[(size_t)(2 * kdp) * N2 + ((j0 + BN + kj) >> 1)];
            krb = *(const uint2*)&kb2[(size_t)(2 * kdp + 1) * N2 + ((j0 + BN + kj) >> 1)];
            vr  = *(const uint4*)&vb2[(size_t)vd * N2 + ((j0 + BN + jv) >> 1)];
        }

        // per-tile half2 l partials (small magnitudes; promoted to fp32 below)
        unsigned lh[2][2] = {{0u, 0u}, {0u, 0u}};  // [rb][row g / row g+8]

        // --- kk-interleaved: S (fp16-accum MMA) -> exp2 -> PV + l(HADD2) ---
#pragma unroll
        for (int kk = 0; kk < 4; kk++) {
            unsigned sd[2][2][2];   // [rb][nn][reg]; reg0 = row g, reg1 = row g+8
#pragma unroll
            for (int rb = 0; rb < 2; rb++)
#pragma unroll
                for (int nn = 0; nn < 2; nn++) {
                    sd[rb][nn][0] = 0u;
                    sd[rb][nn][1] = 0u;
                }

#pragma unroll
            for (int ks = 0; ks < 2; ks++) {
#pragma unroll
                for (int nn = 0; nn < 2; nn++) {
                    int n = 2 * kk + nn;
                    unsigned bfr[2];
                    bfr[0] = ksh2[8 * ks + tig][8 * n + g];
                    bfr[1] = ksh2[8 * ks + tig + 4][8 * n + g];
                    mma_f16h(sd[0][nn], qa[0][ks], bfr, sd[0][nn]);
                    mma_f16h(sd[1][nn], qa[1][ks], bfr, sd[1][nn]);
                }
            }

            // P = exp2(S): D-fragments are already PV A-fragment halves
            unsigned afr[2][4];
#pragma unroll
            for (int rb = 0; rb < 2; rb++) {
                afr[rb][0] = ex2h2(sd[rb][0][0]);
                afr[rb][1] = ex2h2(sd[rb][0][1]);
                afr[rb][2] = ex2h2(sd[rb][1][0]);
                afr[rb][3] = ex2h2(sd[rb][1][1]);
                // l partials on the FMA pipe (was a tensor MMA)
                lh[rb][0] = hadd2(lh[rb][0], hadd2(afr[rb][0], afr[rb][2]));
                lh[rb][1] = hadd2(lh[rb][1], hadd2(afr[rb][1], afr[rb][3]));
            }
#pragma unroll
            for (int nn = 0; nn < 4; nn++) {
                unsigned bfr[2];
                bfr[0] = vh2[8 * nn + g][8 * kk + tig];
                bfr[1] = vh2[8 * nn + g][8 * kk + tig + 4];
                mma_f16(oacc[0][nn], afr[0], bfr, oacc[0][nn]);
                mma_f16(oacc[1][nn], afr[1], bfr, oacc[1][nn]);
            }
        }

        // promote per-tile l partials to fp32
#pragma unroll
        for (int rb = 0; rb < 2; rb++) {
            lf[rb][0] += h2sumf(lh[rb][0]);
            lf[rb][1] += h2sumf(lh[rb][1]);
        }
    }

    // --- Reduce l across the quad (tig lanes), then epilogue ---
#pragma unroll
    for (int rb = 0; rb < 2; rb++)
#pragma unroll
        for (int rr = 0; rr < 2; rr++) {
            lf[rb][rr] += __shfl_xor_sync(0xffffffffu, lf[rb][rr], 1);
            lf[rb][rr] += __shfl_xor_sync(0xffffffffu, lf[rb][rr], 2);
        }

    unsigned* obh = g_atth + (size_t)(b * (INNER / 2) + h * (DHEAD / 2)) * NSEQ;
#pragma unroll
    for (int rb = 0; rb < 2; rb++) {
        const float il0 = 1.f / lf[rb][0];
        const float il1 = 1.f / lf[rb][1];
        const int r0 = i0 + mw + 16 * rb + g;
        const int r1 = r0 + 8;
#pragma unroll
        for (int n = 0; n < 4; n++) {
            int dp = 4 * n + tig;            // d-pair row
            obh[(size_t)dp * NSEQ + r0] = f2h2(oacc[rb][n][1] * il0, oacc[rb][n][0] * il0);
            obh[(size_t)dp * NSEQ + r1] = f2h2(oacc[rb][n][3] * il1, oacc[rb][n][2] * il1);
        }
    }
}

// ---------------------------------------------------------------------------
// Launch: qkv GEMM -> flash attention -> output projection
// ---------------------------------------------------------------------------
extern "C" void kernel_launch(void* const* d_in, const int* in_sizes, int n_in,
                              void* d_out, int out_size) {
    const float* x      = (const float*)d_in[0];  // (4,256,64,64)
    const float* w_qkv  = (const float*)d_in[1];  // (384,256)
    const float* w_out  = (const float*)d_in[2];  // (256,128)
    const float* b_out  = (const float*)d_in[3];  // (256,)
    float* y = (float*)d_out;                     // (4,256,64,64)

    dim3 g1(NSEQ / 128, (3 * INNER) / 128, BATCH); // (32, 3, 4)
    gemm_qkv_tc_kernel<<<g1, 256>>>(w_qkv, x);

    dim3 g2(NSEQ / BM, BATCH * NHEADS);            // (16, 16)
    flash_attn_mma_kernel<<<g2, 256>>>();

    dim3 g3(NSEQ / 128, CIN / 128, BATCH);         // (32, 2, 4)
    gemm_out_tc_kernel<<<g3, 256>>>(w_out, b_out, y);
}